// round 10
// baseline (speedup 1.0000x reference)
#include <cuda_runtime.h>

#define NNZ     4194304
#define DENSE   16
#define DIMLOG  13
#define DIMSZ   8192
#define WORDS   2097152u           // 2^26 cells / 32
#define SCAN_BLOCKS 2048
#define SCAN_WPT 4
#define STAGE_CAP 4096
#define MAIN_BLOCKS (NNZ / 128)    // 16 rows/warp, 8 warps/block
#define TAIL_BLOCKS 256
#define FIX_BLOCKS 512

// Occupancy bitmap (8MB). Zero at entry (module init / re-zeroed each run).
__device__ __align__(16) unsigned g_bitsA[WORDS];
// Scan-written metadata: {bm, exclusive slot offset of bit0} per word (16MB).
__device__ __align__(16) uint2 g_meta2[WORDS];
// Per-entry winner flags, 1 bit/entry packed 8/byte (512KB). Fully rewritten.
__device__ __align__(16) unsigned char g_wflags[NNZ / 8];
// Loser entry ids (worst case NNZ).
__device__ unsigned g_loser[NNZ];
__device__ unsigned g_loser_cnt;     // reset by scatter tail each run
__device__ unsigned g_loser_snap;    // snapshotted by scan for fixup
__device__ unsigned g_desc[SCAN_BLOCKS];
__device__ unsigned g_ticket;
__device__ unsigned g_total;

// ---------------------------------------------------------------------------
__device__ __forceinline__ unsigned block_exscan(unsigned v, unsigned& blocktotal) {
    __shared__ unsigned warp_sums[8];
    __shared__ unsigned warp_off[8];
    unsigned lane = threadIdx.x & 31u, wid = threadIdx.x >> 5;
    unsigned x = v;
#pragma unroll
    for (int d = 1; d < 32; d <<= 1) {
        unsigned y = __shfl_up_sync(0xffffffffu, x, d);
        if ((int)lane >= d) x += y;
    }
    if (lane == 31) warp_sums[wid] = x;
    __syncthreads();
    if (threadIdx.x < 8) {
        unsigned s = warp_sums[threadIdx.x];
        unsigned inc = s;
#pragma unroll
        for (int d = 1; d < 8; d <<= 1) {
            unsigned y = __shfl_up_sync(0xffu, inc, d);
            if ((int)threadIdx.x >= d) inc += y;
        }
        warp_off[threadIdx.x] = inc - s;
    }
    __syncthreads();
    blocktotal = warp_off[7] + warp_sums[7];
    return warp_off[wid] + (x - v);
}

// ---------------------------------------------------------------------------
// B: mark occupancy, elect winners, append losers. 8 entries/thread.
__global__ void k_mark(const int* __restrict__ idx) {
    unsigned i = blockIdx.x * 256u + threadIdx.x;      // entries 8i..8i+7
    int4 r0 = __ldg((const int4*)idx + 2 * i);
    int4 r1 = __ldg((const int4*)idx + 2 * i + 1);
    int4 c0 = __ldg((const int4*)(idx + NNZ) + 2 * i);
    int4 c1 = __ldg((const int4*)(idx + NNZ) + 2 * i + 1);
    unsigned f[8] = {
        ((unsigned)r0.x << DIMLOG) | (unsigned)c0.x,
        ((unsigned)r0.y << DIMLOG) | (unsigned)c0.y,
        ((unsigned)r0.z << DIMLOG) | (unsigned)c0.z,
        ((unsigned)r0.w << DIMLOG) | (unsigned)c0.w,
        ((unsigned)r1.x << DIMLOG) | (unsigned)c1.x,
        ((unsigned)r1.y << DIMLOG) | (unsigned)c1.y,
        ((unsigned)r1.z << DIMLOG) | (unsigned)c1.z,
        ((unsigned)r1.w << DIMLOG) | (unsigned)c1.w };
    unsigned old[8];
#pragma unroll
    for (int j = 0; j < 8; j++)
        old[j] = atomicOr(&g_bitsA[f[j] >> 5], 1u << (f[j] & 31u));
    unsigned win = 0;
#pragma unroll
    for (int j = 0; j < 8; j++)
        if (!((old[j] >> (f[j] & 31u)) & 1u)) win |= 1u << j;
    g_wflags[i] = (unsigned char)win;                  // coalesced byte store

    // Warp-aggregated loser append (rare: ~3% of entries).
    unsigned nl = 8u - (unsigned)__popc(win);
    unsigned lane = threadIdx.x & 31u;
    unsigned pre = nl;
#pragma unroll
    for (int d = 1; d < 32; d <<= 1) {
        unsigned y = __shfl_up_sync(0xffffffffu, pre, d);
        if ((int)lane >= d) pre += y;
    }
    unsigned wtot = __shfl_sync(0xffffffffu, pre, 31);
    unsigned base = 0;
    if (lane == 31 && wtot) base = atomicAdd(&g_loser_cnt, wtot);
    base = __shfl_sync(0xffffffffu, base, 31);
    unsigned my = base + pre - nl;
    if (nl) {
#pragma unroll
        for (int j = 0; j < 8; j++)
            if (!((win >> j) & 1u)) g_loser[my++] = 8u * i + (unsigned)j;
    }
}

// S: single-pass scan (decoupled lookback) + meta2 writes + smem-staged
//    compact of unique indices + n_unique. No dup handling.
__global__ void k_scan_compact(float* __restrict__ out) {
    __shared__ unsigned sh_lbid, sh_prefix;
    __shared__ float s0[STAGE_CAP];
    __shared__ float s1[STAGE_CAP];
    unsigned tid = threadIdx.x;
    if (tid == 0) sh_lbid = atomicAdd(&g_ticket, 1u);
    __syncthreads();
    unsigned lbid = sh_lbid;
    if (lbid == 0 && tid == 0) g_loser_snap = g_loser_cnt;  // mark is complete
    unsigned base = lbid * (256u * SCAN_WPT) + tid * SCAN_WPT;

    uint4 bw = *((const uint4*)(g_bitsA + base));      // 4 words, one LDG.128
    unsigned bm[SCAN_WPT] = {bw.x, bw.y, bw.z, bw.w};
    unsigned s = __popc(bm[0]) + __popc(bm[1]) + __popc(bm[2]) + __popc(bm[3]);
    unsigned tot;
    unsigned ex = block_exscan(s, tot);

    if (tid < 32) {
        if (tid == 0) atomicExch(&g_desc[lbid], (tot << 2) | (lbid == 0 ? 2u : 1u));
        unsigned prefix = 0;
        if (lbid > 0) {
            int look = (int)lbid - 1;
            unsigned running = 0;
            while (true) {
                int j = look - 31 + (int)tid;
                unsigned d;
                if (j < 0) d = 2u;
                else {
                    do { d = *((volatile unsigned*)(g_desc + j)); } while ((d & 3u) == 0u);
                }
                unsigned ball = __ballot_sync(0xffffffffu, (d & 3u) == 2u);
                if (ball) {
                    int hi = 31 - __clz(ball);
                    unsigned contrib = ((int)tid >= hi) ? (d >> 2) : 0u;
                    running += __reduce_add_sync(0xffffffffu, contrib);
                    break;
                } else {
                    running += __reduce_add_sync(0xffffffffu, d >> 2);
                    look -= 32;
                }
            }
            prefix = running;
            if (tid == 0) atomicExch(&g_desc[lbid], ((prefix + tot) << 2) | 2u);
        }
        if (tid == 0) sh_prefix = prefix;
    }
    __syncthreads();

    unsigned prefix = sh_prefix;
    unsigned off = prefix + ex;
    if (lbid == SCAN_BLOCKS - 1 && tid == 0) {
        unsigned nu = prefix + tot;
        g_total = nu;
        out[(size_t)2 * NNZ + (size_t)NNZ * DENSE] = (float)nu;
    }

    float* out0 = out;
    float* out1 = out + NNZ;
    bool staged = (tot <= STAGE_CAP);

    // meta2 writes: pack 4 {bm,off} pairs into two uint4 stores.
    {
        unsigned o = off;
        unsigned offs[SCAN_WPT];
#pragma unroll
        for (int j = 0; j < SCAN_WPT; j++) { offs[j] = o; o += __popc(bm[j]); }
        uint4* dst = (uint4*)(g_meta2 + base);
        uint4 a = {bm[0], offs[0], bm[1], offs[1]};
        uint4 b = {bm[2], offs[2], bm[3], offs[3]};
        dst[0] = a; dst[1] = b;
    }

#pragma unroll
    for (int j = 0; j < SCAN_WPT; j++) {
        unsigned w = base + j;
        unsigned o = off;
        unsigned v = bm[j];
        while (v) {
            unsigned b = (unsigned)__ffs(v) - 1u;
            v &= v - 1u;
            unsigned cell = (w << 5) | b;
            float rf = (float)(cell >> DIMLOG);
            float cf = (float)(cell & (DIMSZ - 1));
            if (staged) {
                unsigned lo = o - prefix;
                s0[lo] = rf; s1[lo] = cf;
            } else {
                __stcs(out0 + o, rf);
                __stcs(out1 + o, cf);
            }
            o++;
        }
        off = o;
    }

    if (staged) {
        __syncthreads();
        for (unsigned i = tid; i < tot; i += 256u) {
            __stcs(out0 + prefix + i, s0[i]);
            __stcs(out1 + prefix + i, s1[i]);
        }
    }
}

// E: scatter. 16 rows/warp; winners plain-store, losers fully skipped.
// Tail blocks: padding fill + state resets for the next run.
__global__ void k_scatter(const int* __restrict__ idx,
                          const float* __restrict__ vals,
                          float* __restrict__ out) {
    float* vout = out + (size_t)2 * NNZ;

    if (blockIdx.x >= MAIN_BLOCKS) {
        unsigned tb = blockIdx.x - MAIN_BLOCKS;
        unsigned t0 = tb * 256u + threadIdx.x;
        unsigned nu = g_total;
        float4 z4 = {0.f, 0.f, 0.f, 0.f};
        for (unsigned slot = nu + t0; slot < NNZ; slot += TAIL_BLOCKS * 256u) {
            __stcs(out + slot, 8192.0f);
            __stcs(out + NNZ + slot, 0.0f);
            float4* v = (float4*)(vout + (size_t)slot * DENSE);
            __stcs(v + 0, z4); __stcs(v + 1, z4); __stcs(v + 2, z4); __stcs(v + 3, z4);
        }
        uint4 z = {0u, 0u, 0u, 0u};
        for (unsigned i = t0; i < WORDS / 4; i += TAIL_BLOCKS * 256u)
            __stcs(((uint4*)g_bitsA) + i, z);
        if (tb == 0) {
            if (threadIdx.x < SCAN_BLOCKS / 4) ((uint4*)g_desc)[threadIdx.x] = z;
            if (threadIdx.x == 0) { g_ticket = 0u; g_loser_cnt = 0u; }
        }
        return;
    }

    unsigned t = blockIdx.x * 256u + threadIdx.x;
    unsigned lane = threadIdx.x & 31u;
    unsigned warpRow0 = (t >> 5) * 16u;

    unsigned packed = 0;
    if (lane < 16) {
        unsigned r = warpRow0 + lane;
        unsigned flat = ((unsigned)__ldg(idx + r) << DIMLOG) | (unsigned)__ldg(idx + NNZ + r);
        unsigned w = flat >> 5, b = flat & 31u;
        uint2 mt = __ldg(&g_meta2[w]);
        unsigned slot = mt.y + __popc(mt.x & ((1u << b) - 1u));
        unsigned winner = (unsigned)(g_wflags[r >> 3] >> (r & 7u)) & 1u;
        packed = (slot << 1) | winner;
    }
    packed = __shfl_sync(0xffffffffu, packed, lane >> 1);
    if (!(packed & 1u)) return;                        // loser: handled by fixup
    unsigned slot = packed >> 1;
    unsigned sub = (lane & 1u) * 2u;
    unsigned i = warpRow0 + (lane >> 1);

    const float4* src = (const float4*)vals + (size_t)i * 4 + sub;
    float4 v0 = __ldcs(src + 0);
    float4 v1 = __ldcs(src + 1);
    float4* dst = (float4*)(vout + (size_t)slot * DENSE + sub * 4);
    __stcs(dst + 0, v0);
    __stcs(dst + 1, v1);
}

// F: losers accumulate on top of winner rows (safe: after scatter).
__global__ void k_fixup(const int* __restrict__ idx,
                        const float* __restrict__ vals,
                        float* __restrict__ out) {
    float* vout = out + (size_t)2 * NNZ;
    unsigned n = g_loser_snap;
    for (unsigned k = blockIdx.x * 256u + threadIdx.x; k < n;
         k += FIX_BLOCKS * 256u) {
        unsigned e = g_loser[k];
        unsigned flat = ((unsigned)__ldg(idx + e) << DIMLOG) | (unsigned)__ldg(idx + NNZ + e);
        unsigned w = flat >> 5, b = flat & 31u;
        uint2 mt = __ldg(&g_meta2[w]);
        unsigned slot = mt.y + __popc(mt.x & ((1u << b) - 1u));
        const float4* src = (const float4*)vals + (size_t)e * 4;
        float* dst = vout + (size_t)slot * DENSE;
#pragma unroll
        for (int q = 0; q < 4; q++) {
            float4 v = __ldg(src + q);
            atomicAdd(dst + q * 4 + 0, v.x);
            atomicAdd(dst + q * 4 + 1, v.y);
            atomicAdd(dst + q * 4 + 2, v.z);
            atomicAdd(dst + q * 4 + 3, v.w);
        }
    }
}

// ---------------------------------------------------------------------------
extern "C" void kernel_launch(void* const* d_in, const int* in_sizes, int n_in,
                              void* d_out, int out_size) {
    (void)in_sizes; (void)n_in; (void)out_size;
    const int*   idx  = (const int*)d_in[0];
    const float* vals = (const float*)d_in[1];
    float* out = (float*)d_out;

    k_mark        <<<NNZ / 8 / 256, 256>>>(idx);
    k_scan_compact<<<SCAN_BLOCKS,   256>>>(out);
    k_scatter     <<<MAIN_BLOCKS + TAIL_BLOCKS, 256>>>(idx, vals, out);
    k_fixup       <<<FIX_BLOCKS,    256>>>(idx, vals, out);
}